// round 15
// baseline (speedup 1.0000x reference)
#include <cuda_runtime.h>
#include <cuda_bf16.h>
#include <math.h>
#include <stdint.h>

// ---------------- problem constants ----------------
#define BSZ   64
#define HW    1024        // 32*32
#define CH    684
#define HIDD  256
#define NPP   512
#define KCONV 121         // 11*11
#define KTOT  805         // 684 + 121
#define KPAD  832         // 26 * 32
#define NCHUNK 26         // K chunks of 32

// ---------------- device scratch ----------------
__device__ __nv_bfloat16 g_Abf[(size_t)BSZ * KPAD * HW];   // [b][k][l] bf16 A
__device__ __nv_bfloat16 g_BmatTb[KPAD * NPP];             // [k][p] bf16 combined B
__device__ float g_pred[BSZ * HIDD];      // [b][j]
__device__ float g_query[BSZ * NPP];      // [b][p]
__device__ float g_D[NPP];                // Ua_b + Uf_b + Uf*convQ_b
__device__ float g_et[4 * BSZ * HW];      // 4 N-block partial slices
__device__ float g_ctx2[BSZ * CH];        // [b][c]
__device__ float g_o[BSZ * HIDD];         // [b][i]

__device__ __forceinline__ uint32_t smem_u32(const void* p) {
    uint32_t a;
    asm("{ .reg .u64 t; cvta.to.shared.u64 t, %1; cvt.u32.u64 %0, t; }" : "=r"(a) : "l"(p));
    return a;
}
// 256B-row swizzle: XOR 16B-granule index with (row % 8)
__device__ __forceinline__ uint32_t swzA(uint32_t o) { return o ^ (((o >> 8) & 7u) << 4); }

__device__ __forceinline__ void cp16(uint32_t dst, const void* src) {
    asm volatile("cp.async.cg.shared.global [%0], [%1], 16;" :: "r"(dst), "l"(src) : "memory");
}
__device__ __forceinline__ void cp_commit() { asm volatile("cp.async.commit_group;" ::: "memory"); }
__device__ __forceinline__ float tanh_fast(float x) {
    float y; asm("tanh.approx.f32 %0, %1;" : "=f"(y) : "f"(x)); return y;
}
// reduce over the 8 k_sub lanes (lane bits 0..2)
__device__ __forceinline__ float red8(float v) {
    v += __shfl_xor_sync(0xffffffffu, v, 1);
    v += __shfl_xor_sync(0xffffffffu, v, 2);
    v += __shfl_xor_sync(0xffffffffu, v, 4);
    return v;
}

// ---------------- K1: prepA half (8 rows/blk) | (half 0 also: foldUf + bmatT) ----------------
#define PREPA_HALF (32 * KPAD / 8)     // 3328 blocks = 32 batches
#define FOLD_OFF   PREPA_HALF          // 3328
#define BMAT_OFF   (FOLD_OFF + NPP)    // 3840
#define PREPB_GRID0 (BMAT_OFF + KPAD)  // 4672 (half 0)
#define PREPB_GRID1 PREPA_HALF         // 3328 (half 1)

__global__ void __launch_bounds__(256) k_prepB(const float* __restrict__ feature,
                                               const float* __restrict__ alpha,
                                               const float* __restrict__ Uf_w,
                                               const float* __restrict__ convQ_w,
                                               const float* __restrict__ Ua_w,
                                               int half) {
    __shared__ float s_buf[256];
    int blk = blockIdx.x;
    int tid = threadIdx.x;

    if (blk < PREPA_HALF) {
        // 8 rows per block, 32 threads per row, 32 elems per thread
        int row = half * (32 * KPAD) + blk * 8 + (tid >> 5);   // global row = b*832 + k
        int k = row % KPAD;
        int b = row / KPAD;
        int l = (tid & 31) * 32;
        #pragma unroll
        for (int seg = 0; seg < 2; seg++) {
            int ls = l + seg * 16;
            float v[16];
            if (k < CH) {
                const float* fr = &feature[((size_t)(b * CH + k)) * HW + ls];
                float4 f0 = *(const float4*)fr;
                float4 f1 = *(const float4*)(fr + 4);
                float4 f2 = *(const float4*)(fr + 8);
                float4 f3 = *(const float4*)(fr + 12);
                v[0]=f0.x; v[1]=f0.y; v[2]=f0.z; v[3]=f0.w;
                v[4]=f1.x; v[5]=f1.y; v[6]=f1.z; v[7]=f1.w;
                v[8]=f2.x; v[9]=f2.y; v[10]=f2.z; v[11]=f2.w;
                v[12]=f3.x; v[13]=f3.y; v[14]=f3.z; v[15]=f3.w;
            } else if (k < KTOT) {
                int t = k - CH;
                int dy = t / 11, dx = t - dy * 11;
                int y  = (ls >> 5) + dy - 5;
                int x0 = (ls & 31) + dx - 5;
                const float* ar = alpha + b * HW + y * 32;
                bool yok = (y >= 0 && y < 32);
                #pragma unroll
                for (int j = 0; j < 16; j++) {
                    int xc = x0 + j;
                    v[j] = (yok && xc >= 0 && xc < 32) ? ar[xc] : 0.f;
                }
            } else {
                #pragma unroll
                for (int j = 0; j < 16; j++) v[j] = 0.f;
            }
            uint32_t u[8];
            #pragma unroll
            for (int j = 0; j < 8; j++) {
                __nv_bfloat162 pp = __nv_bfloat162(__float2bfloat16(v[2 * j]),
                                                   __float2bfloat16(v[2 * j + 1]));
                u[j] = *(uint32_t*)&pp;
            }
            __nv_bfloat16* dst = &g_Abf[((size_t)row) * HW + ls];
            *(uint4*)dst       = make_uint4(u[0], u[1], u[2], u[3]);
            *(uint4*)(dst + 8) = make_uint4(u[4], u[5], u[6], u[7]);
        }
    } else if (blk < BMAT_OFF) {           // half 0 only
        int p = blk - FOLD_OFF;
        s_buf[tid] = Uf_w[p * 256 + tid];
        __syncthreads();
        int t = tid;
        if (t < KCONV) {
            float acc = 0.f;
            #pragma unroll 4
            for (int q = 0; q < 256; q++)
                acc += s_buf[q] * convQ_w[q * KCONV + t];
            g_BmatTb[(CH + t) * NPP + p] = __float2bfloat16(acc);
        }
    } else {                               // half 0 only
        int k = blk - BMAT_OFF;
        for (int p = tid; p < NPP; p += 256) {
            if (k < CH)         g_BmatTb[k * NPP + p] = __float2bfloat16(Ua_w[p * CH + k]);
            else if (k >= KTOT) g_BmatTb[k * NPP + p] = __float2bfloat16(0.f);
        }
    }
}

// ---------------- K2 (stream 2): gru1 (warp-split-K) + D vector ----------------
#define G1_N 512
#define G1D_GRID (G1_N + 64)

__global__ void __launch_bounds__(256) k_gru1d(const int* __restrict__ x,
                                               const float* __restrict__ emb,
                                               const float* __restrict__ hidden,
                                               const float* __restrict__ wih,
                                               const float* __restrict__ whh,
                                               const float* __restrict__ bih,
                                               const float* __restrict__ bhh,
                                               const float* __restrict__ Uf_w,
                                               const float* __restrict__ convQ_b,
                                               const float* __restrict__ Ua_b,
                                               const float* __restrict__ Uf_b) {
    int blk = blockIdx.x;
    int tid = threadIdx.x;
    if (blk < G1_N) {
        int gw = (blk * 256 + tid) >> 5;   // 0..4095
        int lane = tid & 31;
        int j  = gw >> 4;
        int bq = gw & 15;
        int ks = lane & 7, bs = lane >> 3;
        int b = bq * 4 + bs;

        const float* eb = emb + x[b] * 256;
        const float* hb = hidden + b * 256;
        const float* w0 = wih + j * 256;
        const float* w1 = wih + (256 + j) * 256;
        const float* w2 = wih + (512 + j) * 256;
        const float* u0 = whh + j * 256;
        const float* u1 = whh + (256 + j) * 256;
        const float* u2 = whh + (512 + j) * 256;

        float gi0 = 0.f, gi1 = 0.f, gi2 = 0.f, gh0 = 0.f, gh1 = 0.f, gh2 = 0.f;
        #pragma unroll 4
        for (int k = ks; k < 256; k += 8) {
            float e = eb[k], h = hb[k];
            gi0 += e * w0[k]; gi1 += e * w1[k]; gi2 += e * w2[k];
            gh0 += h * u0[k]; gh1 += h * u1[k]; gh2 += h * u2[k];
        }
        gi0 = red8(gi0); gi1 = red8(gi1); gi2 = red8(gi2);
        gh0 = red8(gh0); gh1 = red8(gh1); gh2 = red8(gh2);
        if (ks == 0) {
            gi0 += bih[j]; gi1 += bih[256 + j]; gi2 += bih[512 + j];
            gh0 += bhh[j]; gh1 += bhh[256 + j]; gh2 += bhh[512 + j];
            float r = 1.f / (1.f + expf(-(gi0 + gh0)));
            float z = 1.f / (1.f + expf(-(gi1 + gh1)));
            float n = tanhf(gi2 + r * gh2);
            float hprev = hidden[b * 256 + j];
            g_pred[b * 256 + j] = (1.f - z) * n + z * hprev;
        }
    } else {
        int p = (blk - G1_N) * 8 + (tid >> 5);
        int lane = tid & 31;
        float acc = 0.f;
        for (int q = lane; q < 256; q += 32)
            acc += Uf_w[p * 256 + q] * convQ_b[q];
        #pragma unroll
        for (int o = 16; o; o >>= 1) acc += __shfl_down_sync(0xffffffffu, acc, o);
        if (lane == 0) g_D[p] = acc + Ua_b[p] + Uf_b[p];
    }
}

// ---------------- K3 (stream 2): query (warp-split-K) ----------------
__global__ void __launch_bounds__(256) k_query(const float* __restrict__ Wa_w,
                                               const float* __restrict__ Wa_b) {
    int gw = (blockIdx.x * 256 + threadIdx.x) >> 5;   // 0..8191
    int lane = threadIdx.x & 31;
    int p  = gw >> 4;
    int bq = gw & 15;
    int ks = lane & 7, bs = lane >> 3;
    int b = bq * 4 + bs;

    const float* pr = g_pred + b * 256;
    const float* wr = Wa_w + p * 256;
    float acc = 0.f;
    #pragma unroll 8
    for (int k = ks; k < 256; k += 8) acc += pr[k] * wr[k];
    acc = red8(acc);
    if (ks == 0) g_query[b * NPP + p] = acc + Wa_b[p] + g_D[p];
}

// ---------------- K4: fused attention GEMM half, 4-stage, 2 CTAs/SM ----------------
#define STAGES 4
#define A_ST   8192
#define B_ST   8192
#define B_OFF  (STAGES * A_ST)                 // 32768
#define DSMEM_GEMM (STAGES * (A_ST + B_ST))    // 65536

__global__ void __launch_bounds__(256, 2) k_gemm_bf(const float* __restrict__ Va_w,
                                                    int my0) {
    extern __shared__ char dsm[];
    __shared__ float s_red[128][4];
    uint32_t dynb = smem_u32(dsm);

    int tid = threadIdx.x;
    int wid = tid >> 5, lane = tid & 31;
    int grp = lane >> 2, tig = lane & 3;
    int warp_m = wid >> 2, warp_n = wid & 3;     // 2 x 4
    int phase = lane >> 3, lr = lane & 7;

    int n0 = blockIdx.x * 128;
    int m0 = (blockIdx.y + my0) * 128;
    int b  = m0 >> 10;
    int l0 = m0 & 1023;

    int rT = tid >> 4, cT = tid & 15;
    const __nv_bfloat16* gA = g_Abf + (size_t)b * KPAD * HW + l0;
    const __nv_bfloat16* gB = g_BmatTb + n0;
    uint32_t so0 = swzA((uint32_t)(rT * 256 + cT * 16));
    uint32_t so1 = swzA((uint32_t)((rT + 16) * 256 + cT * 16));

    uint32_t aoff[2][4], boff[2][2];
    #pragma unroll
    for (int ks = 0; ks < 2; ks++) {
        #pragma unroll
        for (int mi = 0; mi < 4; mi++)
            aoff[ks][mi] = swzA((uint32_t)((ks * 16 + (phase >> 1) * 8 + lr) * 256 +
                                           (warp_m * 64 + mi * 16 + (phase & 1) * 8) * 2));
        #pragma unroll
        for (int nj = 0; nj < 2; nj++)
            boff[ks][nj] = swzA((uint32_t)((ks * 16 + (phase & 1) * 8 + lr) * 256 +
                                           (warp_n * 32 + nj * 16 + (phase >> 1) * 8) * 2));
    }

    float c[4][4][4];
    #pragma unroll
    for (int mi = 0; mi < 4; mi++)
        #pragma unroll
        for (int ni = 0; ni < 4; ni++)
            #pragma unroll
            for (int j = 0; j < 4; j++) c[mi][ni][j] = 0.f;

    #define ISSUE(c_)                                                                 \
    {                                                                                 \
        int k0 = (c_) * 32;                                                           \
        int st = (c_) % STAGES;                                                       \
        uint32_t ab = dynb + st * A_ST;                                               \
        uint32_t bb = dynb + B_OFF + st * B_ST;                                       \
        cp16(ab + so0, gA + (size_t)(k0 + rT) * HW + cT * 8);                         \
        cp16(ab + so1, gA + (size_t)(k0 + rT + 16) * HW + cT * 8);                    \
        cp16(bb + so0, gB + (k0 + rT) * NPP + cT * 8);                                \
        cp16(bb + so1, gB + (k0 + rT + 16) * NPP + cT * 8);                           \
        cp_commit();                                                                  \
    }

    ISSUE(0); ISSUE(1); ISSUE(2);

    for (int cc = 0; cc < NCHUNK; cc++) {
        int pend = NCHUNK - 1 - cc; if (pend > STAGES - 2) pend = STAGES - 2;
        switch (pend) {
            case 2: asm volatile("cp.async.wait_group 2;" ::: "memory"); break;
            case 1: asm volatile("cp.async.wait_group 1;" ::: "memory"); break;
            default: asm volatile("cp.async.wait_group 0;" ::: "memory"); break;
        }
        __syncthreads();
        if (cc + STAGES - 1 < NCHUNK) ISSUE(cc + STAGES - 1);

        int st = cc % STAGES;
        uint32_t ab = dynb + st * A_ST;
        uint32_t bb = dynb + B_OFF + st * B_ST;

        #pragma unroll
        for (int ks = 0; ks < 2; ks++) {
            uint32_t a[4][4], br[2][4];
            #pragma unroll
            for (int mi = 0; mi < 4; mi++)
                asm volatile("ldmatrix.sync.aligned.m8n8.x4.trans.shared.b16 {%0,%1,%2,%3}, [%4];"
                             : "=r"(a[mi][0]), "=r"(a[mi][1]), "=r"(a[mi][2]), "=r"(a[mi][3])
                             : "r"(ab + aoff[ks][mi]));
            #pragma unroll
            for (int nj = 0; nj < 2; nj++)
                asm volatile("ldmatrix.sync.aligned.m8n8.x4.trans.shared.b16 {%0,%1,%2,%3}, [%4];"
                             : "=r"(br[nj][0]), "=r"(br[nj][1]), "=r"(br[nj][2]), "=r"(br[nj][3])
                             : "r"(bb + boff[ks][nj]));
            #pragma unroll
            for (int mi = 0; mi < 4; mi++)
                #pragma unroll
                for (int nj = 0; nj < 2; nj++)
                    #pragma unroll
                    for (int h = 0; h < 2; h++) {
                        int ni = nj * 2 + h;
                        asm volatile("mma.sync.aligned.m16n8k16.row.col.f32.bf16.bf16.f32 "
                                     "{%0,%1,%2,%3}, {%4,%5,%6,%7}, {%8,%9}, {%0,%1,%2,%3};"
                                     : "+f"(c[mi][ni][0]), "+f"(c[mi][ni][1]),
                                       "+f"(c[mi][ni][2]), "+f"(c[mi][ni][3])
                                     : "r"(a[mi][0]), "r"(a[mi][1]), "r"(a[mi][2]), "r"(a[mi][3]),
                                       "r"(br[nj][h * 2]), "r"(br[nj][h * 2 + 1]));
                    }
        }
    }

    const float* qrow = g_query + b * NPP;
    #pragma unroll
    for (int mi = 0; mi < 4; mi++) {
        float rs0 = 0.f, rs1 = 0.f;
        #pragma unroll
        for (int ni = 0; ni < 4; ni++) {
            int ng = n0 + warp_n * 32 + ni * 8 + 2 * tig;
            float q0 = qrow[ng],     va0 = Va_w[ng];
            float q1 = qrow[ng + 1], va1 = Va_w[ng + 1];
            rs0 += tanh_fast(c[mi][ni][0] + q0) * va0 + tanh_fast(c[mi][ni][1] + q1) * va1;
            rs1 += tanh_fast(c[mi][ni][2] + q0) * va0 + tanh_fast(c[mi][ni][3] + q1) * va1;
        }
        #pragma unroll
        for (int o = 1; o < 4; o <<= 1) {
            rs0 += __shfl_xor_sync(0xffffffffu, rs0, o);
            rs1 += __shfl_xor_sync(0xffffffffu, rs1, o);
        }
        if (tig == 0) {
            int ml = warp_m * 64 + mi * 16 + grp;
            s_red[ml][warp_n] = rs0;
            s_red[ml + 8][warp_n] = rs1;
        }
    }
    __syncthreads();
    if (tid < 128) {
        float e = s_red[tid][0] + s_red[tid][1] + s_red[tid][2] + s_red[tid][3];
        g_et[blockIdx.x * (BSZ * HW) + m0 + tid] = e;
    }
}

// ---------------- K5: fused softmax + context half (bf16 A rows) ----------------
__global__ void __launch_bounds__(256) k_ctx(const float* __restrict__ Va_b,
                                             float* __restrict__ out_alpha,
                                             int b0) {
    __shared__ float sa[HW];       // unnormalized exp
    __shared__ float sred[256];
    int b = blockIdx.y + b0;
    int tid = threadIdx.x;
    float vab = Va_b[0];
    float ps = 0.f;
    for (int i = tid; i < HW; i += 256) {
        int m = b * HW + i;
        float ex = expf(g_et[m] + g_et[65536 + m] + g_et[131072 + m] + g_et[196608 + m] + vab);
        sa[i] = ex;
        ps += ex;
    }
    sred[tid] = ps;
    __syncthreads();
    for (int o = 128; o; o >>= 1) {
        if (tid < o) sred[tid] += sred[tid + o];
        __syncthreads();
    }
    float denom = sred[0] + 1e-8f;
    float inv = 1.f / denom;

    if (blockIdx.x == 0) {
        for (int i = tid; i < HW; i += 256)
            out_alpha[b * HW + i] = sa[i] * inv;
    }

    int warp = tid >> 5, lane = tid & 31;
    int c = blockIdx.x * 8 + warp;
    if (c < CH) {
        const __nv_bfloat16* fr = g_Abf + ((size_t)(b * KPAD + c)) * HW;
        float acc = 0.f;
        for (int i0 = lane * 8; i0 < HW; i0 += 256) {
            uint4 u = *(const uint4*)(fr + i0);
            __nv_bfloat162 p0 = *(__nv_bfloat162*)&u.x;
            __nv_bfloat162 p1 = *(__nv_bfloat162*)&u.y;
            __nv_bfloat162 p2 = *(__nv_bfloat162*)&u.z;
            __nv_bfloat162 p3 = *(__nv_bfloat162*)&u.w;
            acc += __low2float(p0) * sa[i0]     + __high2float(p0) * sa[i0 + 1]
                 + __low2float(p1) * sa[i0 + 2] + __high2float(p1) * sa[i0 + 3]
                 + __low2float(p2) * sa[i0 + 4] + __high2float(p2) * sa[i0 + 5]
                 + __low2float(p3) * sa[i0 + 6] + __high2float(p3) * sa[i0 + 7];
        }
        #pragma unroll
        for (int o = 16; o; o >>= 1) acc += __shfl_down_sync(0xffffffffu, acc, o);
        if (lane == 0) g_ctx2[b * CH + c] = acc * inv;
    }
}

// ---------------- K6: GRU2 half (warp-split-K) -> out_h2 ----------------
__global__ void __launch_bounds__(256) k_gru2(const float* __restrict__ wih,
                                              const float* __restrict__ whh,
                                              const float* __restrict__ bih,
                                              const float* __restrict__ bhh,
                                              float* __restrict__ out_h2,
                                              int b0) {
    int gw = (blockIdx.x * 256 + threadIdx.x) >> 5;   // 0..2047
    int lane = threadIdx.x & 31;
    int j  = gw >> 3;          // 0..255
    int bq = gw & 7;
    int ks = lane & 7, bs = lane >> 3;
    int b = b0 + bq * 4 + bs;

    const float* cb = g_ctx2 + b * CH;
    const float* pb = g_pred + b * 256;
    const float* w0 = wih + j * CH;
    const float* w1 = wih + (256 + j) * CH;
    const float* w2 = wih + (512 + j) * CH;
    const float* u0 = whh + j * 256;
    const float* u1 = whh + (256 + j) * 256;
    const float* u2 = whh + (512 + j) * 256;

    float gi0 = 0.f, gi1 = 0.f, gi2 = 0.f, gh0 = 0.f, gh1 = 0.f, gh2 = 0.f;
    #pragma unroll 4
    for (int k = ks; k < CH; k += 8) {
        float cv = cb[k];
        gi0 += cv * w0[k]; gi1 += cv * w1[k]; gi2 += cv * w2[k];
    }
    #pragma unroll 4
    for (int k = ks; k < 256; k += 8) {
        float h = pb[k];
        gh0 += h * u0[k]; gh1 += h * u1[k]; gh2 += h * u2[k];
    }
    gi0 = red8(gi0); gi1 = red8(gi1); gi2 = red8(gi2);
    gh0 = red8(gh0); gh1 = red8(gh1); gh2 = red8(gh2);
    if (ks == 0) {
        gi0 += bih[j]; gi1 += bih[256 + j]; gi2 += bih[512 + j];
        gh0 += bhh[j]; gh1 += bhh[256 + j]; gh2 += bhh[512 + j];
        float r = 1.f / (1.f + expf(-(gi0 + gh0)));
        float z = 1.f / (1.f + expf(-(gi1 + gh1)));
        float n = tanhf(gi2 + r * gh2);
        float hprev = g_pred[b * 256 + j];
        out_h2[b * 256 + j] = (1.f - z) * n + z * hprev;
    }
}

// ---------------- K7: ocomp half (warp-split-K): o[b][i] ----------------
__global__ void __launch_bounds__(256) k_ocomp(const int* __restrict__ x,
                                               const float* __restrict__ emb,
                                               const float* __restrict__ h2,
                                               const float* __restrict__ Ws_w,
                                               const float* __restrict__ Ws_b,
                                               const float* __restrict__ Wc_w,
                                               const float* __restrict__ Wc_b,
                                               int b0) {
    int gw = (blockIdx.x * 256 + threadIdx.x) >> 5;   // 0..2047
    int lane = threadIdx.x & 31;
    int i  = gw >> 3;          // 0..255
    int bq = gw & 7;
    int ks = lane & 7, bs = lane >> 3;
    int b = b0 + bq * 4 + bs;

    const float* hb = h2 + b * 256;
    const float* cb = g_ctx2 + b * CH;
    const float* ws = Ws_w + i * 256;
    const float* wc = Wc_w + i * CH;
    float acc = 0.f;
    #pragma unroll 4
    for (int k = ks; k < 256; k += 8) acc += hb[k] * ws[k];
    #pragma unroll 4
    for (int k = ks; k < CH; k += 8) acc += cb[k] * wc[k];
    acc = red8(acc);
    if (ks == 0)
        g_o[b * 256 + i] = acc + emb[x[b] * 256 + i] + Ws_b[i] + Wc_b[i];
}

// ---------------- K8: maxout + logits half (warp-split-K) ----------------
__global__ void __launch_bounds__(256) k_logits(const float* __restrict__ Wo_w,
                                                const float* __restrict__ Wo_b,
                                                float* __restrict__ out_logits,
                                                int b0) {
    int gw = (blockIdx.x * 256 + threadIdx.x) >> 5;   // 0..1023
    int lane = threadIdx.x & 31;
    int v  = gw >> 3;          // 0..127
    int bq = gw & 7;
    int ks = lane & 7, bs = lane >> 3;
    int b = b0 + bq * 4 + bs;

    const float* ob = g_o + b * 256;
    const float* wo = Wo_w + v * 128;
    float acc = 0.f;
    #pragma unroll 4
    for (int i2 = ks; i2 < 128; i2 += 8) {
        float m = fmaxf(ob[2 * i2], ob[2 * i2 + 1]);
        acc += m * wo[i2];
    }
    acc = red8(acc);
    if (ks == 0) out_logits[b * 128 + v] = acc + Wo_b[v];
}

// ---------------- launch ----------------
extern "C" void kernel_launch(void* const* d_in, const int* in_sizes, int n_in,
                              void* d_out, int out_size) {
    (void)in_sizes; (void)n_in; (void)out_size;
    const int*   x        = (const int*)  d_in[0];
    const float* hidden   = (const float*)d_in[1];
    const float* feature  = (const float*)d_in[2];
    const float* alpha    = (const float*)d_in[3];
    const float* emb      = (const float*)d_in[4];
    const float* gru1_wih = (const float*)d_in[5];
    const float* gru1_whh = (const float*)d_in[6];
    const float* gru1_bih = (const float*)d_in[7];
    const float* gru1_bhh = (const float*)d_in[8];
    const float* gru2_wih = (const float*)d_in[9];
    const float* gru2_whh = (const float*)d_in[10];
    const float* gru2_bih = (const float*)d_in[11];
    const float* gru2_bhh = (const float*)d_in[12];
    const float* convQ_w  = (const float*)d_in[13];
    const float* convQ_b  = (const float*)d_in[14];
    const float* Wa_w     = (const float*)d_in[15];
    const float* Wa_b     = (const float*)d_in[16];
    const float* Ua_w     = (const float*)d_in[17];
    const float* Ua_b     = (const float*)d_in[18];
    const float* Uf_w     = (const float*)d_in[19];
    const float* Uf_b     = (const float*)d_in[20];
    const float* Va_w     = (const float*)d_in[21];
    const float* Va_b     = (const float*)d_in[22];
    const float* Ws_w     = (const float*)d_in[23];
    const float* Ws_b     = (const float*)d_in[24];
    const float* Wc_w     = (const float*)d_in[25];
    const float* Wc_b     = (const float*)d_in[26];
    const float* Wo_w     = (const float*)d_in[27];
    const float* Wo_b     = (const float*)d_in[28];

    float* out_logits = (float*)d_out;                    // 64*128
    float* out_h2     = out_logits + 64 * 128;            // 64*256
    float* out_alpha  = out_h2 + 64 * 256;                // 64*1024

    static cudaStream_t s2 = nullptr;
    static cudaEvent_t evF = nullptr, evQ = nullptr, evP1 = nullptr,
                       evG0 = nullptr, evT0 = nullptr;
    if (!s2) {
        cudaFuncSetAttribute(k_gemm_bf, cudaFuncAttributeMaxDynamicSharedMemorySize, DSMEM_GEMM);
        cudaStreamCreateWithFlags(&s2, cudaStreamNonBlocking);
        cudaEventCreateWithFlags(&evF, cudaEventDisableTiming);
        cudaEventCreateWithFlags(&evQ, cudaEventDisableTiming);
        cudaEventCreateWithFlags(&evP1, cudaEventDisableTiming);
        cudaEventCreateWithFlags(&evG0, cudaEventDisableTiming);
        cudaEventCreateWithFlags(&evT0, cudaEventDisableTiming);
    }

    // fork
    cudaEventRecord(evF, 0);
    cudaStreamWaitEvent(s2, evF, 0);

    // stream 0: prep half 0 (+ B matrices)
    k_prepB<<<PREPB_GRID0, 256>>>(feature, alpha, Uf_w, convQ_w, Ua_w, 0);

    // stream 2: gru1+D -> query -> prep half 1
    k_gru1d<<<G1D_GRID, 256, 0, s2>>>(x, emb, hidden,
                                      gru1_wih, gru1_whh, gru1_bih, gru1_bhh,
                                      Uf_w, convQ_b, Ua_b, Uf_b);
    k_query<<<1024, 256, 0, s2>>>(Wa_w, Wa_b);
    cudaEventRecord(evQ, s2);
    k_prepB<<<PREPB_GRID1, 256, 0, s2>>>(feature, alpha, Uf_w, convQ_w, Ua_w, 1);
    cudaEventRecord(evP1, s2);

    // stream 0: GEMM half 0 (needs prep half 0 [in-order] + query)
    cudaStreamWaitEvent(0, evQ, 0);
    k_gemm_bf<<<dim3(4, 256), 256, DSMEM_GEMM>>>(Va_w, 0);
    cudaEventRecord(evG0, 0);

    // stream 0: GEMM half 1 (needs prep half 1)
    cudaStreamWaitEvent(0, evP1, 0);
    k_gemm_bf<<<dim3(4, 256), 256, DSMEM_GEMM>>>(Va_w, 256);

    // stream 2: ctx half 0 + tail half 0, overlapping GEMM half 1 / ctx half 1
    cudaStreamWaitEvent(s2, evG0, 0);
    k_ctx   <<<dim3(86, 32), 256, 0, s2>>>(Va_b, out_alpha, 0);
    k_gru2  <<<256, 256, 0, s2>>>(gru2_wih, gru2_whh, gru2_bih, gru2_bhh, out_h2, 0);
    k_ocomp <<<256, 256, 0, s2>>>(x, emb, out_h2, Ws_w, Ws_b, Wc_w, Wc_b, 0);
    k_logits<<<128, 256, 0, s2>>>(Wo_w, Wo_b, out_logits, 0);
    cudaEventRecord(evT0, s2);

    // stream 0: ctx half 1 + tail half 1, then join
    k_ctx   <<<dim3(86, 32), 256>>>(Va_b, out_alpha, 32);
    k_gru2  <<<256, 256>>>(gru2_wih, gru2_whh, gru2_bih, gru2_bhh, out_h2, 32);
    k_ocomp <<<256, 256>>>(x, emb, out_h2, Ws_w, Ws_b, Wc_w, Wc_b, 32);
    k_logits<<<128, 256>>>(Wo_w, Wo_b, out_logits, 32);
    cudaStreamWaitEvent(0, evT0, 0);
}

// round 16
// speedup vs baseline: 1.1245x; 1.1245x over previous
#include <cuda_runtime.h>
#include <cuda_bf16.h>
#include <math.h>
#include <stdint.h>

// ---------------- problem constants ----------------
#define BSZ   64
#define HW    1024        // 32*32
#define CH    684
#define HIDD  256
#define NPP   512
#define KCONV 121         // 11*11
#define KTOT  805         // 684 + 121
#define KPAD  832         // 26 * 32
#define NCHUNK 26         // K chunks of 32

// ---------------- device scratch ----------------
__device__ __nv_bfloat16 g_Abf[(size_t)BSZ * KPAD * HW];   // [b][k][l] bf16 A
__device__ __nv_bfloat16 g_BmatTb[KPAD * NPP];             // [k][p] bf16 combined B
__device__ float g_pred[BSZ * HIDD];      // [b][j]
__device__ float g_query[BSZ * NPP];      // [b][p]
__device__ float g_D[NPP];                // Ua_b + Uf_b + Uf*convQ_b
__device__ float g_et[4 * BSZ * HW];      // 4 N-block partial slices
__device__ float g_ctx2[BSZ * CH];        // [b][c]
__device__ float g_o[BSZ * HIDD];         // [b][i]

__device__ __forceinline__ uint32_t smem_u32(const void* p) {
    uint32_t a;
    asm("{ .reg .u64 t; cvta.to.shared.u64 t, %1; cvt.u32.u64 %0, t; }" : "=r"(a) : "l"(p));
    return a;
}
// 256B-row swizzle: XOR 16B-granule index with (row % 8)
__device__ __forceinline__ uint32_t swzA(uint32_t o) { return o ^ (((o >> 8) & 7u) << 4); }

__device__ __forceinline__ void cp16(uint32_t dst, const void* src) {
    asm volatile("cp.async.cg.shared.global [%0], [%1], 16;" :: "r"(dst), "l"(src) : "memory");
}
__device__ __forceinline__ void cp_commit() { asm volatile("cp.async.commit_group;" ::: "memory"); }
__device__ __forceinline__ float tanh_fast(float x) {
    float y; asm("tanh.approx.f32 %0, %1;" : "=f"(y) : "f"(x)); return y;
}
// reduce over the 8 k_sub lanes (lane bits 0..2)
__device__ __forceinline__ float red8(float v) {
    v += __shfl_xor_sync(0xffffffffu, v, 1);
    v += __shfl_xor_sync(0xffffffffu, v, 2);
    v += __shfl_xor_sync(0xffffffffu, v, 4);
    return v;
}

// ---------------- K1: prepA half (R14 layout: 4 rows/blk, 16 elems/thread) ----------------
#define PREPA_HALF (32 * KPAD / 4)     // 6656 blocks = 32 batches
#define FOLD_OFF   PREPA_HALF          // 6656
#define BMAT_OFF   (FOLD_OFF + NPP)    // 7168
#define PREPB_GRID0 (BMAT_OFF + KPAD)  // 8000 (half 0)
#define PREPB_GRID1 PREPA_HALF         // 6656 (half 1)

__global__ void __launch_bounds__(256) k_prepB(const float* __restrict__ feature,
                                               const float* __restrict__ alpha,
                                               const float* __restrict__ Uf_w,
                                               const float* __restrict__ convQ_w,
                                               const float* __restrict__ Ua_w,
                                               int half) {
    __shared__ float s_buf[256];
    int blk = blockIdx.x;
    int tid = threadIdx.x;

    if (blk < PREPA_HALF) {
        int row = half * (32 * KPAD) + blk * 4 + (tid >> 6);   // global row = b*832 + k
        int k = row % KPAD;
        int b = row / KPAD;
        int l = (tid & 63) * 16;
        float v[16];
        if (k < CH) {
            const float* fr = &feature[((size_t)(b * CH + k)) * HW + l];
            float4 f0 = *(const float4*)fr;
            float4 f1 = *(const float4*)(fr + 4);
            float4 f2 = *(const float4*)(fr + 8);
            float4 f3 = *(const float4*)(fr + 12);
            v[0]=f0.x; v[1]=f0.y; v[2]=f0.z; v[3]=f0.w;
            v[4]=f1.x; v[5]=f1.y; v[6]=f1.z; v[7]=f1.w;
            v[8]=f2.x; v[9]=f2.y; v[10]=f2.z; v[11]=f2.w;
            v[12]=f3.x; v[13]=f3.y; v[14]=f3.z; v[15]=f3.w;
        } else if (k < KTOT) {
            int t = k - CH;
            int dy = t / 11, dx = t - dy * 11;
            int y  = (l >> 5) + dy - 5;                  // all 16 elems share y
            int x0 = (l & 31) + dx - 5;
            const float* ar = alpha + b * HW + y * 32;
            bool yok = (y >= 0 && y < 32);
            #pragma unroll
            for (int j = 0; j < 16; j++) {
                int xc = x0 + j;
                v[j] = (yok && xc >= 0 && xc < 32) ? ar[xc] : 0.f;
            }
        } else {
            #pragma unroll
            for (int j = 0; j < 16; j++) v[j] = 0.f;
        }
        uint32_t u[8];
        #pragma unroll
        for (int j = 0; j < 8; j++) {
            __nv_bfloat162 pp = __nv_bfloat162(__float2bfloat16(v[2 * j]),
                                               __float2bfloat16(v[2 * j + 1]));
            u[j] = *(uint32_t*)&pp;
        }
        __nv_bfloat16* dst = &g_Abf[((size_t)row) * HW + l];
        *(uint4*)dst       = make_uint4(u[0], u[1], u[2], u[3]);
        *(uint4*)(dst + 8) = make_uint4(u[4], u[5], u[6], u[7]);
    } else if (blk < BMAT_OFF) {           // half 0 only
        int p = blk - FOLD_OFF;
        s_buf[tid] = Uf_w[p * 256 + tid];
        __syncthreads();
        int t = tid;
        if (t < KCONV) {
            float acc = 0.f;
            #pragma unroll 4
            for (int q = 0; q < 256; q++)
                acc += s_buf[q] * convQ_w[q * KCONV + t];
            g_BmatTb[(CH + t) * NPP + p] = __float2bfloat16(acc);
        }
    } else {                               // half 0 only
        int k = blk - BMAT_OFF;
        for (int p = tid; p < NPP; p += 256) {
            if (k < CH)         g_BmatTb[k * NPP + p] = __float2bfloat16(Ua_w[p * CH + k]);
            else if (k >= KTOT) g_BmatTb[k * NPP + p] = __float2bfloat16(0.f);
        }
    }
}

// ---------------- K2 (stream 2): gru1 (warp-split-K) + D vector ----------------
#define G1_N 512
#define G1D_GRID (G1_N + 64)

__global__ void __launch_bounds__(256) k_gru1d(const int* __restrict__ x,
                                               const float* __restrict__ emb,
                                               const float* __restrict__ hidden,
                                               const float* __restrict__ wih,
                                               const float* __restrict__ whh,
                                               const float* __restrict__ bih,
                                               const float* __restrict__ bhh,
                                               const float* __restrict__ Uf_w,
                                               const float* __restrict__ convQ_b,
                                               const float* __restrict__ Ua_b,
                                               const float* __restrict__ Uf_b) {
    int blk = blockIdx.x;
    int tid = threadIdx.x;
    if (blk < G1_N) {
        int gw = (blk * 256 + tid) >> 5;   // 0..4095
        int lane = tid & 31;
        int j  = gw >> 4;
        int bq = gw & 15;
        int ks = lane & 7, bs = lane >> 3;
        int b = bq * 4 + bs;

        const float* eb = emb + x[b] * 256;
        const float* hb = hidden + b * 256;
        const float* w0 = wih + j * 256;
        const float* w1 = wih + (256 + j) * 256;
        const float* w2 = wih + (512 + j) * 256;
        const float* u0 = whh + j * 256;
        const float* u1 = whh + (256 + j) * 256;
        const float* u2 = whh + (512 + j) * 256;

        float gi0 = 0.f, gi1 = 0.f, gi2 = 0.f, gh0 = 0.f, gh1 = 0.f, gh2 = 0.f;
        #pragma unroll 4
        for (int k = ks; k < 256; k += 8) {
            float e = eb[k], h = hb[k];
            gi0 += e * w0[k]; gi1 += e * w1[k]; gi2 += e * w2[k];
            gh0 += h * u0[k]; gh1 += h * u1[k]; gh2 += h * u2[k];
        }
        gi0 = red8(gi0); gi1 = red8(gi1); gi2 = red8(gi2);
        gh0 = red8(gh0); gh1 = red8(gh1); gh2 = red8(gh2);
        if (ks == 0) {
            gi0 += bih[j]; gi1 += bih[256 + j]; gi2 += bih[512 + j];
            gh0 += bhh[j]; gh1 += bhh[256 + j]; gh2 += bhh[512 + j];
            float r = 1.f / (1.f + expf(-(gi0 + gh0)));
            float z = 1.f / (1.f + expf(-(gi1 + gh1)));
            float n = tanhf(gi2 + r * gh2);
            float hprev = hidden[b * 256 + j];
            g_pred[b * 256 + j] = (1.f - z) * n + z * hprev;
        }
    } else {
        int p = (blk - G1_N) * 8 + (tid >> 5);
        int lane = tid & 31;
        float acc = 0.f;
        for (int q = lane; q < 256; q += 32)
            acc += Uf_w[p * 256 + q] * convQ_b[q];
        #pragma unroll
        for (int o = 16; o; o >>= 1) acc += __shfl_down_sync(0xffffffffu, acc, o);
        if (lane == 0) g_D[p] = acc + Ua_b[p] + Uf_b[p];
    }
}

// ---------------- K3 (stream 2): query (warp-split-K) ----------------
__global__ void __launch_bounds__(256) k_query(const float* __restrict__ Wa_w,
                                               const float* __restrict__ Wa_b) {
    int gw = (blockIdx.x * 256 + threadIdx.x) >> 5;   // 0..8191
    int lane = threadIdx.x & 31;
    int p  = gw >> 4;
    int bq = gw & 15;
    int ks = lane & 7, bs = lane >> 3;
    int b = bq * 4 + bs;

    const float* pr = g_pred + b * 256;
    const float* wr = Wa_w + p * 256;
    float acc = 0.f;
    #pragma unroll 8
    for (int k = ks; k < 256; k += 8) acc += pr[k] * wr[k];
    acc = red8(acc);
    if (ks == 0) g_query[b * NPP + p] = acc + Wa_b[p] + g_D[p];
}

// ---------------- K4: fused attention GEMM half, 4-stage, 2 CTAs/SM ----------------
#define STAGES 4
#define A_ST   8192
#define B_ST   8192
#define B_OFF  (STAGES * A_ST)                 // 32768
#define DSMEM_GEMM (STAGES * (A_ST + B_ST))    // 65536

__global__ void __launch_bounds__(256, 2) k_gemm_bf(const float* __restrict__ Va_w,
                                                    int my0) {
    extern __shared__ char dsm[];
    __shared__ float s_red[128][4];
    uint32_t dynb = smem_u32(dsm);

    int tid = threadIdx.x;
    int wid = tid >> 5, lane = tid & 31;
    int grp = lane >> 2, tig = lane & 3;
    int warp_m = wid >> 2, warp_n = wid & 3;     // 2 x 4
    int phase = lane >> 3, lr = lane & 7;

    int n0 = blockIdx.x * 128;
    int m0 = (blockIdx.y + my0) * 128;
    int b  = m0 >> 10;
    int l0 = m0 & 1023;

    int rT = tid >> 4, cT = tid & 15;
    const __nv_bfloat16* gA = g_Abf + (size_t)b * KPAD * HW + l0;
    const __nv_bfloat16* gB = g_BmatTb + n0;
    uint32_t so0 = swzA((uint32_t)(rT * 256 + cT * 16));
    uint32_t so1 = swzA((uint32_t)((rT + 16) * 256 + cT * 16));

    uint32_t aoff[2][4], boff[2][2];
    #pragma unroll
    for (int ks = 0; ks < 2; ks++) {
        #pragma unroll
        for (int mi = 0; mi < 4; mi++)
            aoff[ks][mi] = swzA((uint32_t)((ks * 16 + (phase >> 1) * 8 + lr) * 256 +
                                           (warp_m * 64 + mi * 16 + (phase & 1) * 8) * 2));
        #pragma unroll
        for (int nj = 0; nj < 2; nj++)
            boff[ks][nj] = swzA((uint32_t)((ks * 16 + (phase & 1) * 8 + lr) * 256 +
                                           (warp_n * 32 + nj * 16 + (phase >> 1) * 8) * 2));
    }

    float c[4][4][4];
    #pragma unroll
    for (int mi = 0; mi < 4; mi++)
        #pragma unroll
        for (int ni = 0; ni < 4; ni++)
            #pragma unroll
            for (int j = 0; j < 4; j++) c[mi][ni][j] = 0.f;

    #define ISSUE(c_)                                                                 \
    {                                                                                 \
        int k0 = (c_) * 32;                                                           \
        int st = (c_) % STAGES;                                                       \
        uint32_t ab = dynb + st * A_ST;                                               \
        uint32_t bb = dynb + B_OFF + st * B_ST;                                       \
        cp16(ab + so0, gA + (size_t)(k0 + rT) * HW + cT * 8);                         \
        cp16(ab + so1, gA + (size_t)(k0 + rT + 16) * HW + cT * 8);                    \
        cp16(bb + so0, gB + (k0 + rT) * NPP + cT * 8);                                \
        cp16(bb + so1, gB + (k0 + rT + 16) * NPP + cT * 8);                           \
        cp_commit();                                                                  \
    }

    ISSUE(0); ISSUE(1); ISSUE(2);

    for (int cc = 0; cc < NCHUNK; cc++) {
        int pend = NCHUNK - 1 - cc; if (pend > STAGES - 2) pend = STAGES - 2;
        switch (pend) {
            case 2: asm volatile("cp.async.wait_group 2;" ::: "memory"); break;
            case 1: asm volatile("cp.async.wait_group 1;" ::: "memory"); break;
            default: asm volatile("cp.async.wait_group 0;" ::: "memory"); break;
        }
        __syncthreads();
        if (cc + STAGES - 1 < NCHUNK) ISSUE(cc + STAGES - 1);

        int st = cc % STAGES;
        uint32_t ab = dynb + st * A_ST;
        uint32_t bb = dynb + B_OFF + st * B_ST;

        #pragma unroll
        for (int ks = 0; ks < 2; ks++) {
            uint32_t a[4][4], br[2][4];
            #pragma unroll
            for (int mi = 0; mi < 4; mi++)
                asm volatile("ldmatrix.sync.aligned.m8n8.x4.trans.shared.b16 {%0,%1,%2,%3}, [%4];"
                             : "=r"(a[mi][0]), "=r"(a[mi][1]), "=r"(a[mi][2]), "=r"(a[mi][3])
                             : "r"(ab + aoff[ks][mi]));
            #pragma unroll
            for (int nj = 0; nj < 2; nj++)
                asm volatile("ldmatrix.sync.aligned.m8n8.x4.trans.shared.b16 {%0,%1,%2,%3}, [%4];"
                             : "=r"(br[nj][0]), "=r"(br[nj][1]), "=r"(br[nj][2]), "=r"(br[nj][3])
                             : "r"(bb + boff[ks][nj]));
            #pragma unroll
            for (int mi = 0; mi < 4; mi++)
                #pragma unroll
                for (int nj = 0; nj < 2; nj++)
                    #pragma unroll
                    for (int h = 0; h < 2; h++) {
                        int ni = nj * 2 + h;
                        asm volatile("mma.sync.aligned.m16n8k16.row.col.f32.bf16.bf16.f32 "
                                     "{%0,%1,%2,%3}, {%4,%5,%6,%7}, {%8,%9}, {%0,%1,%2,%3};"
                                     : "+f"(c[mi][ni][0]), "+f"(c[mi][ni][1]),
                                       "+f"(c[mi][ni][2]), "+f"(c[mi][ni][3])
                                     : "r"(a[mi][0]), "r"(a[mi][1]), "r"(a[mi][2]), "r"(a[mi][3]),
                                       "r"(br[nj][h * 2]), "r"(br[nj][h * 2 + 1]));
                    }
        }
    }

    const float* qrow = g_query + b * NPP;
    #pragma unroll
    for (int mi = 0; mi < 4; mi++) {
        float rs0 = 0.f, rs1 = 0.f;
        #pragma unroll
        for (int ni = 0; ni < 4; ni++) {
            int ng = n0 + warp_n * 32 + ni * 8 + 2 * tig;
            float q0 = qrow[ng],     va0 = Va_w[ng];
            float q1 = qrow[ng + 1], va1 = Va_w[ng + 1];
            rs0 += tanh_fast(c[mi][ni][0] + q0) * va0 + tanh_fast(c[mi][ni][1] + q1) * va1;
            rs1 += tanh_fast(c[mi][ni][2] + q0) * va0 + tanh_fast(c[mi][ni][3] + q1) * va1;
        }
        #pragma unroll
        for (int o = 1; o < 4; o <<= 1) {
            rs0 += __shfl_xor_sync(0xffffffffu, rs0, o);
            rs1 += __shfl_xor_sync(0xffffffffu, rs1, o);
        }
        if (tig == 0) {
            int ml = warp_m * 64 + mi * 16 + grp;
            s_red[ml][warp_n] = rs0;
            s_red[ml + 8][warp_n] = rs1;
        }
    }
    __syncthreads();
    if (tid < 128) {
        float e = s_red[tid][0] + s_red[tid][1] + s_red[tid][2] + s_red[tid][3];
        g_et[blockIdx.x * (BSZ * HW) + m0 + tid] = e;
    }
}

// ---------------- K5: fused softmax + context half (bf16 A rows) ----------------
__global__ void __launch_bounds__(256) k_ctx(const float* __restrict__ Va_b,
                                             float* __restrict__ out_alpha,
                                             int b0) {
    __shared__ float sa[HW];       // unnormalized exp
    __shared__ float sred[256];
    int b = blockIdx.y + b0;
    int tid = threadIdx.x;
    float vab = Va_b[0];
    float ps = 0.f;
    for (int i = tid; i < HW; i += 256) {
        int m = b * HW + i;
        float ex = expf(g_et[m] + g_et[65536 + m] + g_et[131072 + m] + g_et[196608 + m] + vab);
        sa[i] = ex;
        ps += ex;
    }
    sred[tid] = ps;
    __syncthreads();
    for (int o = 128; o; o >>= 1) {
        if (tid < o) sred[tid] += sred[tid + o];
        __syncthreads();
    }
    float denom = sred[0] + 1e-8f;
    float inv = 1.f / denom;

    if (blockIdx.x == 0) {
        for (int i = tid; i < HW; i += 256)
            out_alpha[b * HW + i] = sa[i] * inv;
    }

    int warp = tid >> 5, lane = tid & 31;
    int c = blockIdx.x * 8 + warp;
    if (c < CH) {
        const __nv_bfloat16* fr = g_Abf + ((size_t)(b * KPAD + c)) * HW;
        float acc = 0.f;
        for (int i0 = lane * 8; i0 < HW; i0 += 256) {
            uint4 u = *(const uint4*)(fr + i0);
            __nv_bfloat162 p0 = *(__nv_bfloat162*)&u.x;
            __nv_bfloat162 p1 = *(__nv_bfloat162*)&u.y;
            __nv_bfloat162 p2 = *(__nv_bfloat162*)&u.z;
            __nv_bfloat162 p3 = *(__nv_bfloat162*)&u.w;
            acc += __low2float(p0) * sa[i0]     + __high2float(p0) * sa[i0 + 1]
                 + __low2float(p1) * sa[i0 + 2] + __high2float(p1) * sa[i0 + 3]
                 + __low2float(p2) * sa[i0 + 4] + __high2float(p2) * sa[i0 + 5]
                 + __low2float(p3) * sa[i0 + 6] + __high2float(p3) * sa[i0 + 7];
        }
        #pragma unroll
        for (int o = 16; o; o >>= 1) acc += __shfl_down_sync(0xffffffffu, acc, o);
        if (lane == 0) g_ctx2[b * CH + c] = acc * inv;
    }
}

// ---------------- K6: GRU2 half (warp-split-K) -> out_h2 ----------------
__global__ void __launch_bounds__(256) k_gru2(const float* __restrict__ wih,
                                              const float* __restrict__ whh,
                                              const float* __restrict__ bih,
                                              const float* __restrict__ bhh,
                                              float* __restrict__ out_h2,
                                              int b0) {
    int gw = (blockIdx.x * 256 + threadIdx.x) >> 5;   // 0..2047
    int lane = threadIdx.x & 31;
    int j  = gw >> 3;          // 0..255
    int bq = gw & 7;
    int ks = lane & 7, bs = lane >> 3;
    int b = b0 + bq * 4 + bs;

    const float* cb = g_ctx2 + b * CH;
    const float* pb = g_pred + b * 256;
    const float* w0 = wih + j * CH;
    const float* w1 = wih + (256 + j) * CH;
    const float* w2 = wih + (512 + j) * CH;
    const float* u0 = whh + j * 256;
    const float* u1 = whh + (256 + j) * 256;
    const float* u2 = whh + (512 + j) * 256;

    float gi0 = 0.f, gi1 = 0.f, gi2 = 0.f, gh0 = 0.f, gh1 = 0.f, gh2 = 0.f;
    #pragma unroll 4
    for (int k = ks; k < CH; k += 8) {
        float cv = cb[k];
        gi0 += cv * w0[k]; gi1 += cv * w1[k]; gi2 += cv * w2[k];
    }
    #pragma unroll 4
    for (int k = ks; k < 256; k += 8) {
        float h = pb[k];
        gh0 += h * u0[k]; gh1 += h * u1[k]; gh2 += h * u2[k];
    }
    gi0 = red8(gi0); gi1 = red8(gi1); gi2 = red8(gi2);
    gh0 = red8(gh0); gh1 = red8(gh1); gh2 = red8(gh2);
    if (ks == 0) {
        gi0 += bih[j]; gi1 += bih[256 + j]; gi2 += bih[512 + j];
        gh0 += bhh[j]; gh1 += bhh[256 + j]; gh2 += bhh[512 + j];
        float r = 1.f / (1.f + expf(-(gi0 + gh0)));
        float z = 1.f / (1.f + expf(-(gi1 + gh1)));
        float n = tanhf(gi2 + r * gh2);
        float hprev = g_pred[b * 256 + j];
        out_h2[b * 256 + j] = (1.f - z) * n + z * hprev;
    }
}

// ---------------- K7: ocomp half (warp-split-K): o[b][i] ----------------
__global__ void __launch_bounds__(256) k_ocomp(const int* __restrict__ x,
                                               const float* __restrict__ emb,
                                               const float* __restrict__ h2,
                                               const float* __restrict__ Ws_w,
                                               const float* __restrict__ Ws_b,
                                               const float* __restrict__ Wc_w,
                                               const float* __restrict__ Wc_b,
                                               int b0) {
    int gw = (blockIdx.x * 256 + threadIdx.x) >> 5;   // 0..2047
    int lane = threadIdx.x & 31;
    int i  = gw >> 3;          // 0..255
    int bq = gw & 7;
    int ks = lane & 7, bs = lane >> 3;
    int b = b0 + bq * 4 + bs;

    const float* hb = h2 + b * 256;
    const float* cb = g_ctx2 + b * CH;
    const float* ws = Ws_w + i * 256;
    const float* wc = Wc_w + i * CH;
    float acc = 0.f;
    #pragma unroll 4
    for (int k = ks; k < 256; k += 8) acc += hb[k] * ws[k];
    #pragma unroll 4
    for (int k = ks; k < CH; k += 8) acc += cb[k] * wc[k];
    acc = red8(acc);
    if (ks == 0)
        g_o[b * 256 + i] = acc + emb[x[b] * 256 + i] + Ws_b[i] + Wc_b[i];
}

// ---------------- K8: maxout + logits half (warp-split-K) ----------------
__global__ void __launch_bounds__(256) k_logits(const float* __restrict__ Wo_w,
                                                const float* __restrict__ Wo_b,
                                                float* __restrict__ out_logits,
                                                int b0) {
    int gw = (blockIdx.x * 256 + threadIdx.x) >> 5;   // 0..1023
    int lane = threadIdx.x & 31;
    int v  = gw >> 3;          // 0..127
    int bq = gw & 7;
    int ks = lane & 7, bs = lane >> 3;
    int b = b0 + bq * 4 + bs;

    const float* ob = g_o + b * 256;
    const float* wo = Wo_w + v * 128;
    float acc = 0.f;
    #pragma unroll 4
    for (int i2 = ks; i2 < 128; i2 += 8) {
        float m = fmaxf(ob[2 * i2], ob[2 * i2 + 1]);
        acc += m * wo[i2];
    }
    acc = red8(acc);
    if (ks == 0) out_logits[b * 128 + v] = acc + Wo_b[v];
}

// ---------------- launch ----------------
extern "C" void kernel_launch(void* const* d_in, const int* in_sizes, int n_in,
                              void* d_out, int out_size) {
    (void)in_sizes; (void)n_in; (void)out_size;
    const int*   x        = (const int*)  d_in[0];
    const float* hidden   = (const float*)d_in[1];
    const float* feature  = (const float*)d_in[2];
    const float* alpha    = (const float*)d_in[3];
    const float* emb      = (const float*)d_in[4];
    const float* gru1_wih = (const float*)d_in[5];
    const float* gru1_whh = (const float*)d_in[6];
    const float* gru1_bih = (const float*)d_in[7];
    const float* gru1_bhh = (const float*)d_in[8];
    const float* gru2_wih = (const float*)d_in[9];
    const float* gru2_whh = (const float*)d_in[10];
    const float* gru2_bih = (const float*)d_in[11];
    const float* gru2_bhh = (const float*)d_in[12];
    const float* convQ_w  = (const float*)d_in[13];
    const float* convQ_b  = (const float*)d_in[14];
    const float* Wa_w     = (const float*)d_in[15];
    const float* Wa_b     = (const float*)d_in[16];
    const float* Ua_w     = (const float*)d_in[17];
    const float* Ua_b     = (const float*)d_in[18];
    const float* Uf_w     = (const float*)d_in[19];
    const float* Uf_b     = (const float*)d_in[20];
    const float* Va_w     = (const float*)d_in[21];
    const float* Va_b     = (const float*)d_in[22];
    const float* Ws_w     = (const float*)d_in[23];
    const float* Ws_b     = (const float*)d_in[24];
    const float* Wc_w     = (const float*)d_in[25];
    const float* Wc_b     = (const float*)d_in[26];
    const float* Wo_w     = (const float*)d_in[27];
    const float* Wo_b     = (const float*)d_in[28];

    float* out_logits = (float*)d_out;                    // 64*128
    float* out_h2     = out_logits + 64 * 128;            // 64*256
    float* out_alpha  = out_h2 + 64 * 256;                // 64*1024

    static cudaStream_t s2 = nullptr;
    static cudaEvent_t evF = nullptr, evQ = nullptr, evP1 = nullptr,
                       evG0 = nullptr, evT0 = nullptr;
    if (!s2) {
        cudaFuncSetAttribute(k_gemm_bf, cudaFuncAttributeMaxDynamicSharedMemorySize, DSMEM_GEMM);
        cudaStreamCreateWithFlags(&s2, cudaStreamNonBlocking);
        cudaEventCreateWithFlags(&evF, cudaEventDisableTiming);
        cudaEventCreateWithFlags(&evQ, cudaEventDisableTiming);
        cudaEventCreateWithFlags(&evP1, cudaEventDisableTiming);
        cudaEventCreateWithFlags(&evG0, cudaEventDisableTiming);
        cudaEventCreateWithFlags(&evT0, cudaEventDisableTiming);
    }

    // fork
    cudaEventRecord(evF, 0);
    cudaStreamWaitEvent(s2, evF, 0);

    // stream 0: prep half 0 (+ B matrices)
    k_prepB<<<PREPB_GRID0, 256>>>(feature, alpha, Uf_w, convQ_w, Ua_w, 0);

    // stream 2: gru1+D -> query -> prep half 1
    k_gru1d<<<G1D_GRID, 256, 0, s2>>>(x, emb, hidden,
                                      gru1_wih, gru1_whh, gru1_bih, gru1_bhh,
                                      Uf_w, convQ_b, Ua_b, Uf_b);
    k_query<<<1024, 256, 0, s2>>>(Wa_w, Wa_b);
    cudaEventRecord(evQ, s2);
    k_prepB<<<PREPB_GRID1, 256, 0, s2>>>(feature, alpha, Uf_w, convQ_w, Ua_w, 1);
    cudaEventRecord(evP1, s2);

    // stream 0: GEMM half 0 (needs prep half 0 [in-order] + query)
    cudaStreamWaitEvent(0, evQ, 0);
    k_gemm_bf<<<dim3(4, 256), 256, DSMEM_GEMM>>>(Va_w, 0);
    cudaEventRecord(evG0, 0);

    // stream 0: GEMM half 1 (needs prep half 1)
    cudaStreamWaitEvent(0, evP1, 0);
    k_gemm_bf<<<dim3(4, 256), 256, DSMEM_GEMM>>>(Va_w, 256);

    // stream 2: ctx half 0 + tail half 0, overlapping GEMM half 1 / ctx half 1
    cudaStreamWaitEvent(s2, evG0, 0);
    k_ctx   <<<dim3(86, 32), 256, 0, s2>>>(Va_b, out_alpha, 0);
    k_gru2  <<<256, 256, 0, s2>>>(gru2_wih, gru2_whh, gru2_bih, gru2_bhh, out_h2, 0);
    k_ocomp <<<256, 256, 0, s2>>>(x, emb, out_h2, Ws_w, Ws_b, Wc_w, Wc_b, 0);
    k_logits<<<128, 256, 0, s2>>>(Wo_w, Wo_b, out_logits, 0);
    cudaEventRecord(evT0, s2);

    // stream 0: ctx half 1 + tail half 1, then join
    k_ctx   <<<dim3(86, 32), 256>>>(Va_b, out_alpha, 32);
    k_gru2  <<<256, 256>>>(gru2_wih, gru2_whh, gru2_bih, gru2_bhh, out_h2, 32);
    k_ocomp <<<256, 256>>>(x, emb, out_h2, Ws_w, Ws_b, Wc_w, Wc_b, 32);
    k_logits<<<128, 256>>>(Wo_w, Wo_b, out_logits, 32);
    cudaStreamWaitEvent(0, evT0, 0);
}